// round 15
// baseline (speedup 1.0000x reference)
#include <cuda_runtime.h>
#include <cuda_fp16.h>
#include <cstdint>

using h16  = __half;
using h162 = __half2;

#define S0 3072
#define S1 4096
#define S2 4096
#define S3 2048
#define S4 1000
#define S4P 1024
#define NB 1024
#define STEPS 20

#define TILE_B    16384                    // 128 rows x 128B (one operand tile)
#define BUF_BYTES (4 * TILE_B)             // Ah, Al, Bh, Bl = 65536
#define NSTAGE    3
#define SMEM_SZ   (1024 + NSTAGE * BUF_BYTES)
#define GRID_P    148

#define DEVARR __device__ __align__(16)

// ------------------------- persistent state (zero-init) --------------------
DEVARR float g_xs1[NB*S1];
DEVARR float g_xs2[NB*S2];
DEVARR float g_xs3[NB*S3];
DEVARR float g_xs4[NB*S4P];                 // padded; pad cols stay 0
DEVARR h16 g_tx1h[NB*S1], g_tx1l[NB*S1];
DEVARR h16 g_tx2h[NB*S2], g_tx2l[NB*S2];
DEVARR h16 g_tx3h[NB*S3], g_tx3l[NB*S3];
DEVARR h16 g_tx4h[NB*S4P], g_tx4l[NB*S4P]; // pad cols stay 0
DEVARR h16 g_es0h[NB*S0], g_es0l[NB*S0];
DEVARR h16 g_es1h[NB*S1], g_es1l[NB*S1];   // init chain: split of raw xs1
DEVARR h16 g_es2h[NB*S2], g_es2l[NB*S2];
DEVARR h16 g_es3h[NB*S3], g_es3l[NB*S3];
DEVARR h16 g_obsh[NB*S0], g_obsl[NB*S0];
// NT weights: W_i as [N=sizes[i-1], K=sizes[i]] (K-major)
DEVARR h16 g_w1h[S0*S1], g_w1l[S0*S1];
DEVARR h16 g_w2h[S1*S2], g_w2l[S1*S2];
DEVARR h16 g_w3h[S2*S3], g_w3l[S2*S3];
DEVARR h16 g_w4h[S3*S4P], g_w4l[S3*S4P];   // K padded, pad cols 0
// NN weights: W_i^T as [N=sizes[i], K=sizes[i-1]]
DEVARR h16 g_w1th[S1*S0], g_w1tl[S1*S0];
DEVARR h16 g_w2th[S2*S1], g_w2tl[S2*S1];
DEVARR h16 g_w3th[S3*S2], g_w3tl[S3*S2];
DEVARR h16 g_w4th[S4P*S3], g_w4tl[S4P*S3]; // N padded, pad rows 0

__device__ unsigned g_tick[64];             // per-launch ticket counters

// ------------------------------- PTX helpers -------------------------------
__device__ __forceinline__ uint32_t s2u(const void* p) {
    uint32_t a;
    asm("{ .reg .u64 t; cvta.to.shared.u64 t, %1; cvt.u32.u64 %0, t; }" : "=r"(a) : "l"(p));
    return a;
}
__device__ __forceinline__ void cp16(uint32_t d, const void* s) {
    asm volatile("cp.async.cg.shared.global [%0], [%1], 16;" :: "r"(d), "l"(s));
}
__device__ __forceinline__ void cp_commit() { asm volatile("cp.async.commit_group;" ::: "memory"); }
template <int N> __device__ __forceinline__ void cp_wait() {
    asm volatile("cp.async.wait_group %0;" :: "n"(N) : "memory");
}
__device__ __forceinline__ void ldsm4(uint32_t* r, uint32_t addr) {
    asm volatile("ldmatrix.sync.aligned.m8n8.x4.shared.b16 {%0,%1,%2,%3}, [%4];"
                 : "=r"(r[0]), "=r"(r[1]), "=r"(r[2]), "=r"(r[3]) : "r"(addr));
}
// main term: fp16 inputs, fp32 accumulator (products exact: 11+11 < 24 bits)
__device__ __forceinline__ void mma_f32acc(float* d, const uint32_t* a,
                                           uint32_t b0, uint32_t b1) {
    asm volatile("mma.sync.aligned.m16n8k16.row.col.f32.f16.f16.f32 "
                 "{%0,%1,%2,%3}, {%4,%5,%6,%7}, {%8,%9}, {%0,%1,%2,%3};"
                 : "+f"(d[0]), "+f"(d[1]), "+f"(d[2]), "+f"(d[3])
                 : "r"(a[0]), "r"(a[1]), "r"(a[2]), "r"(a[3]), "r"(b0), "r"(b1));
}
// cross terms: fp16 inputs, fp16 accumulator (2 d-regs; potentially 2x rate)
__device__ __forceinline__ void mma_f16acc(uint32_t* d, const uint32_t* a,
                                           uint32_t b0, uint32_t b1) {
    asm volatile("mma.sync.aligned.m16n8k16.row.col.f16.f16.f16.f16 "
                 "{%0,%1}, {%2,%3,%4,%5}, {%6,%7}, {%0,%1};"
                 : "+r"(d[0]), "+r"(d[1])
                 : "r"(a[0]), "r"(a[1]), "r"(a[2]), "r"(a[3]), "r"(b0), "r"(b1));
}

// --------------------- JAX threefry + normal (verified) --------------------
__host__ __device__ __forceinline__ uint32_t rotl32(uint32_t v, int s) {
#ifdef __CUDA_ARCH__
    return __funnelshift_l(v, v, s);
#else
    return (v << s) | (v >> (32 - s));
#endif
}
__host__ __device__ __forceinline__ void threefry2x32(
    uint32_t k0, uint32_t k1, uint32_t c0, uint32_t c1, uint32_t& o0, uint32_t& o1)
{
    uint32_t k2 = k0 ^ k1 ^ 0x1BD11BDAu;
    uint32_t x0 = c0 + k0, x1 = c1 + k1;
#define TF_R4(ra, rb, rc, rd)                          \
    x0 += x1; x1 = rotl32(x1, ra); x1 ^= x0;           \
    x0 += x1; x1 = rotl32(x1, rb); x1 ^= x0;           \
    x0 += x1; x1 = rotl32(x1, rc); x1 ^= x0;           \
    x0 += x1; x1 = rotl32(x1, rd); x1 ^= x0;
    TF_R4(13,15,26,6)  x0 += k1; x1 += k2 + 1u;
    TF_R4(17,29,16,24) x0 += k2; x1 += k0 + 2u;
    TF_R4(13,15,26,6)  x0 += k0; x1 += k1 + 3u;
    TF_R4(17,29,16,24) x0 += k1; x1 += k2 + 4u;
    TF_R4(13,15,26,6)  x0 += k2; x1 += k0 + 5u;
#undef TF_R4
    o0 = x0; o1 = x1;
}
__device__ __forceinline__ float erfinv_f32(float x) {
    float w = -log1pf(-x * x), p;
    if (w < 5.0f) {
        w -= 2.5f;
        p = 2.81022636e-08f;
        p = fmaf(p, w, 3.43273939e-07f);  p = fmaf(p, w, -3.5233877e-06f);
        p = fmaf(p, w, -4.39150654e-06f); p = fmaf(p, w, 0.00021858087f);
        p = fmaf(p, w, -0.00125372503f);  p = fmaf(p, w, -0.00417768164f);
        p = fmaf(p, w, 0.246640727f);     p = fmaf(p, w, 1.50140941f);
    } else {
        w = sqrtf(w) - 3.0f;
        p = -0.000200214257f;
        p = fmaf(p, w, 0.000100950558f);  p = fmaf(p, w, 0.00134934322f);
        p = fmaf(p, w, -0.00367342844f);  p = fmaf(p, w, 0.00573950773f);
        p = fmaf(p, w, -0.0076224613f);   p = fmaf(p, w, 0.00943887047f);
        p = fmaf(p, w, 1.00167406f);      p = fmaf(p, w, 2.83297682f);
    }
    return p * x;
}
__device__ __forceinline__ float jax_normal_elem(uint32_t k0, uint32_t k1, uint32_t j) {
    uint32_t x0, x1;
    threefry2x32(k0, k1, 0u, j, x0, x1);
    uint32_t bits = x0 ^ x1;
    float f = __uint_as_float((bits >> 9) | 0x3f800000u) - 1.0f;
    float u = fmaxf(-0.99999994f, f * 2.0f + (-0.99999994f));
    return 1.41421356f * erfinv_f32(u);
}

// ------------------------------ split helper -------------------------------
__device__ __forceinline__ void split2(float a, float b, h16* h, h16* l, size_t off) {
    h16 ha = __float2half_rn(a), hb = __float2half_rn(b);
    h162 hv; hv.x = ha; hv.y = hb;
    *(h162*)(h + off) = hv;
    h162 lv;
    lv.x = __float2half_rn(a - __half2float(ha));
    lv.y = __float2half_rn(b - __half2float(hb));
    *(h162*)(l + off) = lv;
}

// ------------------- smem tile load (128B rows, 16B xor swizzle) -----------
__device__ __forceinline__ void load_tile(const h16* g, int row0, int K, int c,
                                          uint32_t sdst, int tid) {
    const char* gp = (const char*)(g + (size_t)row0 * K) + (size_t)c * 128;
    const size_t strideB = (size_t)K * 2;
#pragma unroll
    for (int i = tid; i < 128 * 8; i += 256) {
        int r = i >> 3, u = i & 7;
        cp16(sdst + r * 128 + ((u ^ (r & 7)) << 4), gp + (size_t)r * strideB + u * 16);
    }
}
__device__ __forceinline__ void load_chunk(const h16* Ah, const h16* Al,
                                           const h16* Bh, const h16* Bl,
                                           int row0, int col0, int K, int c,
                                           uint32_t buf, int tid) {
    load_tile(Ah, row0, K, c, buf, tid);
    load_tile(Al, row0, K, c, buf + TILE_B, tid);
    load_tile(Bh, col0, K, c, buf + 2*TILE_B, tid);
    load_tile(Bl, col0, K, c, buf + 3*TILE_B, tid);
    cp_commit();
}

// ------------------------- batched sub-GEMM descriptors --------------------
struct SubG {
    const h16 *Ah, *Al, *Bh, *Bl;
    const float *bias, *xs_in;
    float *xs_out;
    const h16 *esh, *esl, *txh, *txl;
    h16 *o1h, *o1l, *o2h, *o2l;
    int K, N, beg, nx;
    uint32_t nk0, nk1;
};
struct Phase { SubG g[4]; float nscale; int nsub; int slot; int total; };

// ---------------------------------------------------------------------------
// gemm_b<EPI>: persistent CTAs, atomic-ticket tiles. CTA tile 128x128,
// warp tile 32x64. D = Ah@Bh^T (f32 acc) + [Ah@Bl^T + Al@Bh^T] (f16 acc)
// EPI 0: init    xs_out=D; o1=split(D) (if o1h); o2=split(tanh(D))
// EPI 1: NT es   e = xs_in - (D+bias) + noise*nscale; o1=split(e)
// EPI 2: NN      xn = xs + 0.1*(-es + D*(1-t^2)); xs=xn; o2=split(tanh(xn))
// ---------------------------------------------------------------------------
template <int EPI>
__global__ void __launch_bounds__(256, 1) gemm_b(const __grid_constant__ Phase d)
{
    extern __shared__ char smem[];
    __shared__ int s_tile;
    const uint32_t sb = (s2u(smem) + 1023u) & ~1023u;
    const int tid = threadIdx.x;
    const int warp = tid >> 5, lane = tid & 31;
    const int wm = warp & 3, wn = warp >> 2;   // warp tile: 32 rows x 64 cols
    const int lr = lane & 15, lu = lane >> 4;

    for (;;) {
        if (tid == 0) s_tile = (int)atomicAdd(&g_tick[d.slot], 1u);
        __syncthreads();
        const int t = s_tile;
        if (t >= d.total) return;

        int gi = 0;
#pragma unroll
        for (int i = 1; i < 4; i++)
            if (i < d.nsub && t >= d.g[i].beg) gi = i;
        const SubG& g = d.g[gi];
        const int local = t - g.beg;
        const int row0 = (local / g.nx) * 128;
        const int col0 = (local % g.nx) * 128;
        const int K = g.K, N = g.N;

        float acc[2][8][4];          // main term, f32
        uint32_t xacc[2][8][2];      // shared cross-term acc, f16x2 pairs
#pragma unroll
        for (int a = 0; a < 2; a++)
#pragma unroll
            for (int b = 0; b < 8; b++) {
#pragma unroll
                for (int e = 0; e < 4; e++) acc[a][b][e] = 0.0f;
                xacc[a][b][0] = 0u; xacc[a][b][1] = 0u;
            }

        const int NC = K >> 6;
        load_chunk(g.Ah, g.Al, g.Bh, g.Bl, row0, col0, K, 0, sb, tid);
        load_chunk(g.Ah, g.Al, g.Bh, g.Bl, row0, col0, K, 1, sb + BUF_BYTES, tid);

        int stage = 0;                 // stage of chunk c
        for (int c = 0; c < NC; c++) {
            if (c + 1 < NC) cp_wait<1>(); else cp_wait<0>();
            __syncthreads();
            // safe to overwrite stage (c+2)%3: every warp has passed chunk
            // c-1's mma (distance-3 reuse, issue-after-sync)
            if (c + 2 < NC) {
                int ns = stage + 2; if (ns >= NSTAGE) ns -= NSTAGE;
                load_chunk(g.Ah, g.Al, g.Bh, g.Bl, row0, col0, K, c + 2,
                           sb + (uint32_t)ns * BUF_BYTES, tid);
            }
            const uint32_t buf = sb + (uint32_t)stage * BUF_BYTES;
#pragma unroll
            for (int ks = 0; ks < 4; ks++) {
                const int u = ks * 2 + lu;
                uint32_t ah[2][4], al[2][4], bh[4][4], bl[4][4];
#pragma unroll
                for (int mf = 0; mf < 2; mf++) {
                    const int r = wm * 32 + mf * 16 + lr;
                    const uint32_t sw = (uint32_t)r * 128u + (uint32_t)((u ^ (r & 7)) << 4);
                    ldsm4(ah[mf], buf + sw);
                    ldsm4(al[mf], buf + TILE_B + sw);
                }
#pragma unroll
                for (int nfp = 0; nfp < 4; nfp++) {
                    const int rn = wn * 64 + nfp * 16 + lr;
                    const uint32_t sw = (uint32_t)rn * 128u + (uint32_t)((u ^ (rn & 7)) << 4);
                    ldsm4(bh[nfp], buf + 2*TILE_B + sw);
                    ldsm4(bl[nfp], buf + 3*TILE_B + sw);
                }
                // pass 1: main Ah@Bh, f32 acc
#pragma unroll
                for (int mf = 0; mf < 2; mf++)
#pragma unroll
                    for (int nfp = 0; nfp < 4; nfp++)
#pragma unroll
                        for (int h = 0; h < 2; h++)
                            mma_f32acc(acc[mf][nfp*2+h], ah[mf], bh[nfp][h], bh[nfp][h+2]);
                // pass 2: cross Ah@Bl, f16 acc
#pragma unroll
                for (int mf = 0; mf < 2; mf++)
#pragma unroll
                    for (int nfp = 0; nfp < 4; nfp++)
#pragma unroll
                        for (int h = 0; h < 2; h++)
                            mma_f16acc(xacc[mf][nfp*2+h], ah[mf], bl[nfp][h], bl[nfp][h+2]);
                // pass 3: cross Al@Bh, f16 acc (shared accumulator)
#pragma unroll
                for (int mf = 0; mf < 2; mf++)
#pragma unroll
                    for (int nfp = 0; nfp < 4; nfp++)
#pragma unroll
                        for (int h = 0; h < 2; h++)
                            mma_f16acc(xacc[mf][nfp*2+h], al[mf], bh[nfp][h], bh[nfp][h+2]);
            }
            if (++stage >= NSTAGE) stage = 0;
        }

        // --------------------------- fused epilogue ------------------------
        const int mb = row0 + wm * 32 + (lane >> 2);
        const int nb = col0 + wn * 64 + (lane & 3) * 2;

#pragma unroll
        for (int mf = 0; mf < 2; mf++)
#pragma unroll
            for (int nf = 0; nf < 8; nf++)
#pragma unroll
                for (int eh = 0; eh < 2; eh++) {
                    const int m = mb + mf * 16 + eh * 8;
                    const int n = nb + nf * 8;
                    h162 x2 = *(const h162*)&xacc[mf][nf][eh];
                    float v0 = acc[mf][nf][eh * 2]     + __half2float(x2.x);
                    float v1 = acc[mf][nf][eh * 2 + 1] + __half2float(x2.y);
                    const size_t off = (size_t)m * N + n;
                    if (EPI == 0) {
                        g.xs_out[off] = v0; g.xs_out[off + 1] = v1;
                        if (g.o1h) split2(v0, v1, g.o1h, g.o1l, off);
                        split2(tanhf(v0), tanhf(v1), g.o2h, g.o2l, off);
                    } else if (EPI == 1) {
                        float2 xv = *(const float2*)(g.xs_in + off);
                        float p0 = v0 + g.bias[n], p1 = v1 + g.bias[n + 1];
                        float z0 = jax_normal_elem(g.nk0, g.nk1, (uint32_t)off);
                        float z1 = jax_normal_elem(g.nk0, g.nk1, (uint32_t)off + 1u);
                        split2((xv.x - p0) + z0 * d.nscale, (xv.y - p1) + z1 * d.nscale,
                               g.o1h, g.o1l, off);
                    } else {
                        float2 xv = *(const float2*)(g.xs_in + off);
                        h162 th2 = *(const h162*)(g.txh + off), tl2 = *(const h162*)(g.txl + off);
                        float t0 = __half2float(th2.x) + __half2float(tl2.x);
                        float t1 = __half2float(th2.y) + __half2float(tl2.y);
                        float e0 = 0.f, e1 = 0.f;
                        if (g.esh) {
                            h162 eh2 = *(const h162*)(g.esh + off), el2 = *(const h162*)(g.esl + off);
                            e0 = __half2float(eh2.x) + __half2float(el2.x);
                            e1 = __half2float(eh2.y) + __half2float(el2.y);
                        }
                        float xn0 = xv.x + 0.1f * (-e0 + v0 * (1.0f - t0 * t0));
                        float xn1 = xv.y + 0.1f * (-e1 + v1 * (1.0f - t1 * t1));
                        *(float2*)(g.xs_out + off) = make_float2(xn0, xn1);
                        split2(tanhf(xn0), tanhf(xn1), g.o2h, g.o2l, off);
                    }
                }
        __syncthreads();   // protect s_tile + smem before next tile
    }
}

// ------------------------------ preprocessing ------------------------------
__global__ void k_zero_ticks() { if (threadIdx.x < 64) g_tick[threadIdx.x] = 0u; }

__global__ void k_split(const float* __restrict__ x, h16* __restrict__ h,
                        h16* __restrict__ l, int n) {
    int i = blockIdx.x * 256 + threadIdx.x;
    if (i < n) {
        float v = x[i];
        h16 a = __float2half_rn(v);
        h[i] = a; l[i] = __float2half_rn(v - __half2float(a));
    }
}
__global__ void k_split_pad(const float* __restrict__ x, h16* __restrict__ h,
                            h16* __restrict__ l, int rows, int cols, int ldo) {
    int i = blockIdx.x * 256 + threadIdx.x;
    if (i < rows * cols) {
        int r = i / cols, c = i - r * cols;
        float v = x[i];
        h16 a = __float2half_rn(v);
        size_t o = (size_t)r * ldo + c;
        h[o] = a; l[o] = __float2half_rn(v - __half2float(a));
    }
}
__global__ void k_tsplit(const float* __restrict__ w, h16* __restrict__ th,
                         h16* __restrict__ tl, int K, int N) {
    __shared__ float t[32][33];
    int bx = blockIdx.x * 32, by = blockIdx.y * 32;
    int x = threadIdx.x, y = threadIdx.y;
    for (int yy = y; yy < 32; yy += 8) {
        int k = by + yy, n = bx + x;
        t[yy][x] = (k < K && n < N) ? w[(size_t)k * N + n] : 0.0f;
    }
    __syncthreads();
    for (int yy = y; yy < 32; yy += 8) {
        int n = bx + yy, k = by + x;
        if (n < N && k < K) {
            float v = t[x][yy];
            h16 a = __float2half_rn(v);
            size_t o = (size_t)n * K + k;
            th[o] = a; tl[o] = __float2half_rn(v - __half2float(a));
        }
    }
}
__global__ void k_pack(const float* __restrict__ xs4, float* __restrict__ out) {
    int i = blockIdx.x * 256 + threadIdx.x;
    if (i < NB * S4) { int mm = i / S4, n = i - mm * S4; out[i] = xs4[(size_t)mm * S4P + n]; }
}

// ---------------------------------- host -----------------------------------
template <typename T, size_t N>
static T* sym(T (&arr)[N]) { void* p = nullptr; cudaGetSymbolAddress(&p, arr); return (T*)p; }

static void fill_sub(SubG& s,
                     const h16* Ah, const h16* Al, const h16* Bh, const h16* Bl,
                     int K, int N, const float* bias, const float* xs_in, float* xs_out,
                     const h16* esh, const h16* esl, const h16* txh, const h16* txl,
                     h16* o1h, h16* o1l, h16* o2h, h16* o2l,
                     uint32_t nk0, uint32_t nk1, int& cta)
{
    s.Ah = Ah; s.Al = Al; s.Bh = Bh; s.Bl = Bl;
    s.bias = bias; s.xs_in = xs_in; s.xs_out = xs_out;
    s.esh = esh; s.esl = esl; s.txh = txh; s.txl = txl;
    s.o1h = o1h; s.o1l = o1l; s.o2h = o2h; s.o2l = o2l;
    s.K = K; s.N = N; s.beg = cta; s.nx = N / 128;
    s.nk0 = nk0; s.nk1 = nk1;
    cta += (N / 128) * (NB / 128);
}

extern "C" void kernel_launch(void* const* d_in, const int* in_sizes, int n_in,
                              void* d_out, int out_size)
{
    const float* obs = (const float*)d_in[0];
    const float* W1 = (const float*)d_in[1]; const float* b1 = (const float*)d_in[2];
    const float* W2 = (const float*)d_in[3]; const float* b2 = (const float*)d_in[4];
    const float* W3 = (const float*)d_in[5]; const float* b3 = (const float*)d_in[6];
    const float* W4 = (const float*)d_in[7]; const float* b4 = (const float*)d_in[8];

    float *xs1 = sym(g_xs1), *xs2 = sym(g_xs2), *xs3 = sym(g_xs3), *xs4 = sym(g_xs4);
    h16 *tx1h = sym(g_tx1h), *tx1l = sym(g_tx1l), *tx2h = sym(g_tx2h), *tx2l = sym(g_tx2l);
    h16 *tx3h = sym(g_tx3h), *tx3l = sym(g_tx3l), *tx4h = sym(g_tx4h), *tx4l = sym(g_tx4l);
    h16 *es0h = sym(g_es0h), *es0l = sym(g_es0l), *es1h = sym(g_es1h), *es1l = sym(g_es1l);
    h16 *es2h = sym(g_es2h), *es2l = sym(g_es2l), *es3h = sym(g_es3h), *es3l = sym(g_es3l);
    h16 *obsh = sym(g_obsh), *obsl = sym(g_obsl);
    h16 *w1h = sym(g_w1h), *w1l = sym(g_w1l), *w2h = sym(g_w2h), *w2l = sym(g_w2l);
    h16 *w3h = sym(g_w3h), *w3l = sym(g_w3l), *w4h = sym(g_w4h), *w4l = sym(g_w4l);
    h16 *w1th = sym(g_w1th), *w1tl = sym(g_w1tl), *w2th = sym(g_w2th), *w2tl = sym(g_w2tl);
    h16 *w3th = sym(g_w3th), *w3tl = sym(g_w3tl), *w4th = sym(g_w4th), *w4tl = sym(g_w4tl);

    cudaFuncSetAttribute(gemm_b<0>, cudaFuncAttributeMaxDynamicSharedMemorySize, SMEM_SZ);
    cudaFuncSetAttribute(gemm_b<1>, cudaFuncAttributeMaxDynamicSharedMemorySize, SMEM_SZ);
    cudaFuncSetAttribute(gemm_b<2>, cudaFuncAttributeMaxDynamicSharedMemorySize, SMEM_SZ);

    int slot = 0;
    const dim3 tb(32, 8);
    k_zero_ticks<<<1, 64>>>();
    // weight / input preprocessing (constant per launch)
    k_split<<<(NB*S0 + 255)/256, 256>>>(obs, obsh, obsl, NB*S0);
    k_split<<<(S0*S1 + 255)/256, 256>>>(W1, w1h, w1l, S0*S1);
    k_split<<<(S1*S2 + 255)/256, 256>>>(W2, w2h, w2l, S1*S2);
    k_split<<<(S2*S3 + 255)/256, 256>>>(W3, w3h, w3l, S2*S3);
    k_split_pad<<<(S3*S4 + 255)/256, 256>>>(W4, w4h, w4l, S3, S4, S4P);
    k_tsplit<<<dim3(S1/32, S0/32), tb>>>(W1, w1th, w1tl, S0, S1);
    k_tsplit<<<dim3(S2/32, S1/32), tb>>>(W2, w2th, w2tl, S1, S2);
    k_tsplit<<<dim3(S3/32, S2/32), tb>>>(W3, w3th, w3tl, S2, S3);
    k_tsplit<<<dim3((S4+31)/32, S3/32), tb>>>(W4, w4th, w4tl, S3, S4);

    // ---- init chain (sequential): xs_i = xs_{i-1} @ W_i ----
    {
        Phase ph; ph.nscale = 0.f; ph.nsub = 1; int cta;
        cta = 0; fill_sub(ph.g[0], obsh, obsl, w1th, w1tl, S0, S1, nullptr, nullptr, xs1,
                          nullptr, nullptr, nullptr, nullptr, es1h, es1l, tx1h, tx1l, 0u, 0u, cta);
        ph.slot = slot++; ph.total = cta;
        gemm_b<0><<<GRID_P, 256, SMEM_SZ>>>(ph);
        cta = 0; fill_sub(ph.g[0], es1h, es1l, w2th, w2tl, S1, S2, nullptr, nullptr, xs2,
                          nullptr, nullptr, nullptr, nullptr, es2h, es2l, tx2h, tx2l, 0u, 0u, cta);
        ph.slot = slot++; ph.total = cta;
        gemm_b<0><<<GRID_P, 256, SMEM_SZ>>>(ph);
        cta = 0; fill_sub(ph.g[0], es2h, es2l, w3th, w3tl, S2, S3, nullptr, nullptr, xs3,
                          nullptr, nullptr, nullptr, nullptr, es3h, es3l, tx3h, tx3l, 0u, 0u, cta);
        ph.slot = slot++; ph.total = cta;
        gemm_b<0><<<GRID_P, 256, SMEM_SZ>>>(ph);
        cta = 0; fill_sub(ph.g[0], es3h, es3l, w4th, w4tl, S3, S4P, nullptr, nullptr, xs4,
                          nullptr, nullptr, nullptr, nullptr, nullptr, nullptr, tx4h, tx4l, 0u, 0u, cta);
        ph.slot = slot++; ph.total = cta;
        gemm_b<0><<<GRID_P, 256, SMEM_SZ>>>(ph);
    }

    for (int i = 0; i < STEPS; i++) {
        float nscale = 0.034f * (1.0f - (float)i / 20.0f);
        uint32_t ki0, ki1, kl0[4], kl1[4];
        threefry2x32(0u, 42u, 0u, (uint32_t)i, ki0, ki1);
        for (int li = 0; li < 4; li++) threefry2x32(ki0, ki1, 0u, (uint32_t)li, kl0[li], kl1[li]);

        // ---- top-down (4 independent NT GEMMs, one launch; largest K first)
        {
            Phase ph; ph.nscale = nscale; ph.nsub = 4; int cta = 0;
            fill_sub(ph.g[0], tx2h, tx2l, w2h, w2l, S2,  S1, b2, xs1, nullptr,
                     nullptr, nullptr, nullptr, nullptr, es1h, es1l, nullptr, nullptr,
                     kl0[1], kl1[1], cta);
            fill_sub(ph.g[1], tx1h, tx1l, w1h, w1l, S1,  S0, b1, obs, nullptr,
                     nullptr, nullptr, nullptr, nullptr, es0h, es0l, nullptr, nullptr,
                     kl0[0], kl1[0], cta);
            fill_sub(ph.g[2], tx3h, tx3l, w3h, w3l, S3,  S2, b3, xs2, nullptr,
                     nullptr, nullptr, nullptr, nullptr, es2h, es2l, nullptr, nullptr,
                     kl0[2], kl1[2], cta);
            fill_sub(ph.g[3], tx4h, tx4l, w4h, w4l, S4P, S3, b4, xs3, nullptr,
                     nullptr, nullptr, nullptr, nullptr, es3h, es3l, nullptr, nullptr,
                     kl0[3], kl1[3], cta);
            ph.slot = slot++; ph.total = cta;
            gemm_b<1><<<GRID_P, 256, SMEM_SZ>>>(ph);
        }
        // ---- bottom-up (4 independent NN GEMMs, one launch; largest K first)
        {
            Phase ph; ph.nscale = 0.f; ph.nsub = 4; int cta = 0;
            fill_sub(ph.g[0], es1h, es1l, w2th, w2tl, S1, S2, nullptr, xs2, xs2,
                     es2h, es2l, tx2h, tx2l, nullptr, nullptr, tx2h, tx2l, 0u, 0u, cta);
            fill_sub(ph.g[1], es2h, es2l, w3th, w3tl, S2, S3, nullptr, xs3, xs3,
                     es3h, es3l, tx3h, tx3l, nullptr, nullptr, tx3h, tx3l, 0u, 0u, cta);
            fill_sub(ph.g[2], es0h, es0l, w1th, w1tl, S0, S1, nullptr, xs1, xs1,
                     es1h, es1l, tx1h, tx1l, nullptr, nullptr, tx1h, tx1l, 0u, 0u, cta);
            fill_sub(ph.g[3], es3h, es3l, w4th, w4tl, S3, S4P, nullptr, xs4, xs4,
                     nullptr, nullptr, tx4h, tx4l, nullptr, nullptr, tx4h, tx4l, 0u, 0u, cta);
            ph.slot = slot++; ph.total = cta;
            gemm_b<2><<<GRID_P, 256, SMEM_SZ>>>(ph);
        }
    }
    k_pack<<<(NB*S4 + 255)/256, 256>>>(xs4, (float*)d_out);
}

// round 16
// speedup vs baseline: 1.0202x; 1.0202x over previous
#include <cuda_runtime.h>
#include <cuda_fp16.h>
#include <cstdint>

using h16  = __half;
using h162 = __half2;

#define S0 3072
#define S1 4096
#define S2 4096
#define S3 2048
#define S4 1000
#define S4P 1024
#define NB 1024
#define STEPS 20

#define TILE_B    16384                    // 128 rows x 128B (one operand tile)
#define BUF_BYTES (4 * TILE_B)             // Ah, Al, Bh, Bl = 65536
#define NSTAGE    3
#define SMEM_SZ   (1024 + NSTAGE * BUF_BYTES)
#define GRID_P    152

#define DEVARR __device__ __align__(16)

// ------------------------- persistent state (zero-init) --------------------
DEVARR float g_xs1[NB*S1];
DEVARR float g_xs2[NB*S2];
DEVARR float g_xs3[NB*S3];
DEVARR float g_xs4[NB*S4P];                 // padded; pad cols stay 0
DEVARR h16 g_tx1h[NB*S1], g_tx1l[NB*S1];
DEVARR h16 g_tx2h[NB*S2], g_tx2l[NB*S2];
DEVARR h16 g_tx3h[NB*S3], g_tx3l[NB*S3];
DEVARR h16 g_tx4h[NB*S4P], g_tx4l[NB*S4P]; // pad cols stay 0
DEVARR h16 g_es0h[NB*S0], g_es0l[NB*S0];
DEVARR h16 g_es1h[NB*S1], g_es1l[NB*S1];   // init chain: split of raw xs1
DEVARR h16 g_es2h[NB*S2], g_es2l[NB*S2];
DEVARR h16 g_es3h[NB*S3], g_es3l[NB*S3];
DEVARR h16 g_obsh[NB*S0], g_obsl[NB*S0];
// NT weights: W_i as [N=sizes[i-1], K=sizes[i]] (K-major)
DEVARR h16 g_w1h[S0*S1], g_w1l[S0*S1];
DEVARR h16 g_w2h[S1*S2], g_w2l[S1*S2];
DEVARR h16 g_w3h[S2*S3], g_w3l[S2*S3];
DEVARR h16 g_w4h[S3*S4P], g_w4l[S3*S4P];   // K padded, pad cols 0
// NN weights: W_i^T as [N=sizes[i], K=sizes[i-1]]
DEVARR h16 g_w1th[S1*S0], g_w1tl[S1*S0];
DEVARR h16 g_w2th[S2*S1], g_w2tl[S2*S1];
DEVARR h16 g_w3th[S3*S2], g_w3tl[S3*S2];
DEVARR h16 g_w4th[S4P*S3], g_w4tl[S4P*S3]; // N padded, pad rows 0

__device__ unsigned g_tick[64];             // per-launch ticket counters

// ------------------------------- PTX helpers -------------------------------
__device__ __forceinline__ uint32_t s2u(const void* p) {
    uint32_t a;
    asm("{ .reg .u64 t; cvta.to.shared.u64 t, %1; cvt.u32.u64 %0, t; }" : "=r"(a) : "l"(p));
    return a;
}
__device__ __forceinline__ void cp16(uint32_t d, const void* s) {
    asm volatile("cp.async.cg.shared.global [%0], [%1], 16;" :: "r"(d), "l"(s));
}
__device__ __forceinline__ void cp_commit() { asm volatile("cp.async.commit_group;" ::: "memory"); }
template <int N> __device__ __forceinline__ void cp_wait() {
    asm volatile("cp.async.wait_group %0;" :: "n"(N) : "memory");
}
__device__ __forceinline__ void ldsm4(uint32_t* r, uint32_t addr) {
    asm volatile("ldmatrix.sync.aligned.m8n8.x4.shared.b16 {%0,%1,%2,%3}, [%4];"
                 : "=r"(r[0]), "=r"(r[1]), "=r"(r[2]), "=r"(r[3]) : "r"(addr));
}
// main term: fp16 inputs, fp32 accumulator (products exact: 11+11 < 24 bits)
__device__ __forceinline__ void mma_f32acc(float* d, const uint32_t* a,
                                           uint32_t b0, uint32_t b1) {
    asm volatile("mma.sync.aligned.m16n8k16.row.col.f32.f16.f16.f32 "
                 "{%0,%1,%2,%3}, {%4,%5,%6,%7}, {%8,%9}, {%0,%1,%2,%3};"
                 : "+f"(d[0]), "+f"(d[1]), "+f"(d[2]), "+f"(d[3])
                 : "r"(a[0]), "r"(a[1]), "r"(a[2]), "r"(a[3]), "r"(b0), "r"(b1));
}
// cross terms: fp16 inputs, fp16 accumulator (equal rate; fewer acc regs)
__device__ __forceinline__ void mma_f16acc(uint32_t* d, const uint32_t* a,
                                           uint32_t b0, uint32_t b1) {
    asm volatile("mma.sync.aligned.m16n8k16.row.col.f16.f16.f16.f16 "
                 "{%0,%1}, {%2,%3,%4,%5}, {%6,%7}, {%0,%1};"
                 : "+r"(d[0]), "+r"(d[1])
                 : "r"(a[0]), "r"(a[1]), "r"(a[2]), "r"(a[3]), "r"(b0), "r"(b1));
}

// --------------------- JAX threefry + normal (verified) --------------------
__host__ __device__ __forceinline__ uint32_t rotl32(uint32_t v, int s) {
#ifdef __CUDA_ARCH__
    return __funnelshift_l(v, v, s);
#else
    return (v << s) | (v >> (32 - s));
#endif
}
__host__ __device__ __forceinline__ void threefry2x32(
    uint32_t k0, uint32_t k1, uint32_t c0, uint32_t c1, uint32_t& o0, uint32_t& o1)
{
    uint32_t k2 = k0 ^ k1 ^ 0x1BD11BDAu;
    uint32_t x0 = c0 + k0, x1 = c1 + k1;
#define TF_R4(ra, rb, rc, rd)                          \
    x0 += x1; x1 = rotl32(x1, ra); x1 ^= x0;           \
    x0 += x1; x1 = rotl32(x1, rb); x1 ^= x0;           \
    x0 += x1; x1 = rotl32(x1, rc); x1 ^= x0;           \
    x0 += x1; x1 = rotl32(x1, rd); x1 ^= x0;
    TF_R4(13,15,26,6)  x0 += k1; x1 += k2 + 1u;
    TF_R4(17,29,16,24) x0 += k2; x1 += k0 + 2u;
    TF_R4(13,15,26,6)  x0 += k0; x1 += k1 + 3u;
    TF_R4(17,29,16,24) x0 += k1; x1 += k2 + 4u;
    TF_R4(13,15,26,6)  x0 += k2; x1 += k0 + 5u;
#undef TF_R4
    o0 = x0; o1 = x1;
}
__device__ __forceinline__ float erfinv_f32(float x) {
    float w = -log1pf(-x * x), p;
    if (w < 5.0f) {
        w -= 2.5f;
        p = 2.81022636e-08f;
        p = fmaf(p, w, 3.43273939e-07f);  p = fmaf(p, w, -3.5233877e-06f);
        p = fmaf(p, w, -4.39150654e-06f); p = fmaf(p, w, 0.00021858087f);
        p = fmaf(p, w, -0.00125372503f);  p = fmaf(p, w, -0.00417768164f);
        p = fmaf(p, w, 0.246640727f);     p = fmaf(p, w, 1.50140941f);
    } else {
        w = sqrtf(w) - 3.0f;
        p = -0.000200214257f;
        p = fmaf(p, w, 0.000100950558f);  p = fmaf(p, w, 0.00134934322f);
        p = fmaf(p, w, -0.00367342844f);  p = fmaf(p, w, 0.00573950773f);
        p = fmaf(p, w, -0.0076224613f);   p = fmaf(p, w, 0.00943887047f);
        p = fmaf(p, w, 1.00167406f);      p = fmaf(p, w, 2.83297682f);
    }
    return p * x;
}
__device__ __forceinline__ float jax_normal_elem(uint32_t k0, uint32_t k1, uint32_t j) {
    uint32_t x0, x1;
    threefry2x32(k0, k1, 0u, j, x0, x1);
    uint32_t bits = x0 ^ x1;
    float f = __uint_as_float((bits >> 9) | 0x3f800000u) - 1.0f;
    float u = fmaxf(-0.99999994f, f * 2.0f + (-0.99999994f));
    return 1.41421356f * erfinv_f32(u);
}

// ------------------------------ split helper -------------------------------
__device__ __forceinline__ void split2(float a, float b, h16* h, h16* l, size_t off) {
    h16 ha = __float2half_rn(a), hb = __float2half_rn(b);
    h162 hv; hv.x = ha; hv.y = hb;
    *(h162*)(h + off) = hv;
    h162 lv;
    lv.x = __float2half_rn(a - __half2float(ha));
    lv.y = __float2half_rn(b - __half2float(hb));
    *(h162*)(l + off) = lv;
}

// ------------------- smem tile load (128B rows, 16B xor swizzle) -----------
__device__ __forceinline__ void load_tile(const h16* g, int row0, int K, int c,
                                          uint32_t sdst, int tid) {
    const char* gp = (const char*)(g + (size_t)row0 * K) + (size_t)c * 128;
    const size_t strideB = (size_t)K * 2;
#pragma unroll
    for (int i = tid; i < 128 * 8; i += 256) {
        int r = i >> 3, u = i & 7;
        cp16(sdst + r * 128 + ((u ^ (r & 7)) << 4), gp + (size_t)r * strideB + u * 16);
    }
}

// ------------------------- batched sub-GEMM descriptors --------------------
struct SubG {
    const h16 *Ah, *Al, *Bh, *Bl;
    const float *bias, *xs_in;
    float *xs_out;
    const h16 *esh, *esl, *txh, *txl;
    h16 *o1h, *o1l, *o2h, *o2l;
    int K, N, beg, nx;
    uint32_t nk0, nk1;
};
struct Phase { SubG g[4]; float nscale; int nsub; int slot; int total; };

__device__ __forceinline__ void load_chunk_g(const SubG* g, int row0, int col0,
                                             int c, uint32_t buf, int tid) {
    load_tile(g->Ah, row0, g->K, c, buf, tid);
    load_tile(g->Al, row0, g->K, c, buf + TILE_B, tid);
    load_tile(g->Bh, col0, g->K, c, buf + 2*TILE_B, tid);
    load_tile(g->Bl, col0, g->K, c, buf + 3*TILE_B, tid);
    cp_commit();
}

// ---------------------------------------------------------------------------
// gemm_b<EPI>: persistent CTAs, atomic-ticket tiles, CROSS-TILE software
// pipeline (next tile's first 2 chunks are prefetched during the epilogue).
// CTA tile 128x128, warp tile 32x64.
// D = Ah@Bh^T (f32 acc) + [Ah@Bl^T + Al@Bh^T] (f16 acc)
// EPI 0: init    xs_out=D; o1=split(D) (if o1h); o2=split(tanh(D))
// EPI 1: NT es   e = xs_in - (D+bias) + noise*nscale; o1=split(e)
// EPI 2: NN      xn = xs + 0.1*(-es + D*(1-t^2)); xs=xn; o2=split(tanh(xn))
// ---------------------------------------------------------------------------
template <int EPI>
__global__ void __launch_bounds__(256, 1) gemm_b(const __grid_constant__ Phase d)
{
    extern __shared__ char smem[];
    __shared__ int s_tile;
    const uint32_t sb = (s2u(smem) + 1023u) & ~1023u;
    const int tid = threadIdx.x;
    const int warp = tid >> 5, lane = tid & 31;
    const int wm = warp & 3, wn = warp >> 2;   // warp tile: 32 rows x 64 cols
    const int lr = lane & 15, lu = lane >> 4;

    // ---- first ticket ----
    if (tid == 0) s_tile = (int)atomicAdd(&g_tick[d.slot], 1u);
    __syncthreads();
    int t = s_tile;
    if (t >= d.total) return;

    int gi = 0;
#pragma unroll
    for (int i = 1; i < 4; i++)
        if (i < d.nsub && t >= d.g[i].beg) gi = i;
    const SubG* g = &d.g[gi];
    int local = t - g->beg;
    int row0 = (local / g->nx) * 128;
    int col0 = (local % g->nx) * 128;

    int stage = 0;
    load_chunk_g(g, row0, col0, 0, sb, tid);
    load_chunk_g(g, row0, col0, 1, sb + BUF_BYTES, tid);

    float acc[2][8][4];          // main term, f32
    uint32_t xacc[2][8][2];      // shared cross-term acc, f16x2 pairs

    for (;;) {
#pragma unroll
        for (int a = 0; a < 2; a++)
#pragma unroll
            for (int b = 0; b < 8; b++) {
#pragma unroll
                for (int e = 0; e < 4; e++) acc[a][b][e] = 0.0f;
                xacc[a][b][0] = 0u; xacc[a][b][1] = 0u;
            }

        // -------------------------- mainloop -------------------------------
        const int NC = g->K >> 6;
        for (int c = 0; c < NC; c++) {
            if (c + 1 < NC) cp_wait<1>(); else cp_wait<0>();
            __syncthreads();
            if (c + 2 < NC) {
                int ns = stage + 2; if (ns >= NSTAGE) ns -= NSTAGE;
                load_chunk_g(g, row0, col0, c + 2, sb + (uint32_t)ns * BUF_BYTES, tid);
            }
            const uint32_t buf = sb + (uint32_t)stage * BUF_BYTES;
#pragma unroll
            for (int ks = 0; ks < 4; ks++) {
                const int u = ks * 2 + lu;
                uint32_t ah[2][4], al[2][4], bh[4][4], bl[4][4];
#pragma unroll
                for (int mf = 0; mf < 2; mf++) {
                    const int r = wm * 32 + mf * 16 + lr;
                    const uint32_t sw = (uint32_t)r * 128u + (uint32_t)((u ^ (r & 7)) << 4);
                    ldsm4(ah[mf], buf + sw);
                    ldsm4(al[mf], buf + TILE_B + sw);
                }
#pragma unroll
                for (int nfp = 0; nfp < 4; nfp++) {
                    const int rn = wn * 64 + nfp * 16 + lr;
                    const uint32_t sw = (uint32_t)rn * 128u + (uint32_t)((u ^ (rn & 7)) << 4);
                    ldsm4(bh[nfp], buf + 2*TILE_B + sw);
                    ldsm4(bl[nfp], buf + 3*TILE_B + sw);
                }
#pragma unroll
                for (int mf = 0; mf < 2; mf++)
#pragma unroll
                    for (int nfp = 0; nfp < 4; nfp++)
#pragma unroll
                        for (int h = 0; h < 2; h++)
                            mma_f32acc(acc[mf][nfp*2+h], ah[mf], bh[nfp][h], bh[nfp][h+2]);
#pragma unroll
                for (int mf = 0; mf < 2; mf++)
#pragma unroll
                    for (int nfp = 0; nfp < 4; nfp++)
#pragma unroll
                        for (int h = 0; h < 2; h++)
                            mma_f16acc(xacc[mf][nfp*2+h], ah[mf], bl[nfp][h], bl[nfp][h+2]);
#pragma unroll
                for (int mf = 0; mf < 2; mf++)
#pragma unroll
                    for (int nfp = 0; nfp < 4; nfp++)
#pragma unroll
                        for (int h = 0; h < 2; h++)
                            mma_f16acc(xacc[mf][nfp*2+h], al[mf], bh[nfp][h], bh[nfp][h+2]);
            }
            if (++stage >= NSTAGE) stage = 0;
        }

        // ---- fetch NEXT ticket and prefetch its first 2 chunks while the
        // ---- epilogue (registers/global only) runs
        if (tid == 0) s_tile = (int)atomicAdd(&g_tick[d.slot], 1u);
        __syncthreads();                    // also closes mainloop smem reads
        const int tn = s_tile;
        const bool more = (tn < d.total);
        const SubG* gn = g;
        int gin = gi, row0n = row0, col0n = col0;
        if (more) {
            gin = 0;
#pragma unroll
            for (int i = 1; i < 4; i++)
                if (i < d.nsub && tn >= d.g[i].beg) gin = i;
            gn = &d.g[gin];
            int ln = tn - gn->beg;
            row0n = (ln / gn->nx) * 128;
            col0n = (ln % gn->nx) * 128;
            int s1 = stage + 1; if (s1 >= NSTAGE) s1 -= NSTAGE;
            load_chunk_g(gn, row0n, col0n, 0, sb + (uint32_t)stage * BUF_BYTES, tid);
            load_chunk_g(gn, row0n, col0n, 1, sb + (uint32_t)s1 * BUF_BYTES, tid);
        }

        // --------------------------- fused epilogue ------------------------
        {
            const int N = g->N;
            const int mb = row0 + wm * 32 + (lane >> 2);
            const int nb = col0 + wn * 64 + (lane & 3) * 2;
#pragma unroll
            for (int mf = 0; mf < 2; mf++)
#pragma unroll
                for (int nf = 0; nf < 8; nf++)
#pragma unroll
                    for (int eh = 0; eh < 2; eh++) {
                        const int m = mb + mf * 16 + eh * 8;
                        const int n = nb + nf * 8;
                        h162 x2 = *(const h162*)&xacc[mf][nf][eh];
                        float v0 = acc[mf][nf][eh * 2]     + __half2float(x2.x);
                        float v1 = acc[mf][nf][eh * 2 + 1] + __half2float(x2.y);
                        const size_t off = (size_t)m * N + n;
                        if (EPI == 0) {
                            g->xs_out[off] = v0; g->xs_out[off + 1] = v1;
                            if (g->o1h) split2(v0, v1, g->o1h, g->o1l, off);
                            split2(tanhf(v0), tanhf(v1), g->o2h, g->o2l, off);
                        } else if (EPI == 1) {
                            float2 xv = *(const float2*)(g->xs_in + off);
                            float p0 = v0 + g->bias[n], p1 = v1 + g->bias[n + 1];
                            float z0 = jax_normal_elem(g->nk0, g->nk1, (uint32_t)off);
                            float z1 = jax_normal_elem(g->nk0, g->nk1, (uint32_t)off + 1u);
                            split2((xv.x - p0) + z0 * d.nscale, (xv.y - p1) + z1 * d.nscale,
                                   g->o1h, g->o1l, off);
                        } else {
                            float2 xv = *(const float2*)(g->xs_in + off);
                            h162 th2 = *(const h162*)(g->txh + off), tl2 = *(const h162*)(g->txl + off);
                            float t0 = __half2float(th2.x) + __half2float(tl2.x);
                            float t1 = __half2float(th2.y) + __half2float(tl2.y);
                            float e0 = 0.f, e1 = 0.f;
                            if (g->esh) {
                                h162 eh2 = *(const h162*)(g->esh + off), el2 = *(const h162*)(g->esl + off);
                                e0 = __half2float(eh2.x) + __half2float(el2.x);
                                e1 = __half2float(eh2.y) + __half2float(el2.y);
                            }
                            float xn0 = xv.x + 0.1f * (-e0 + v0 * (1.0f - t0 * t0));
                            float xn1 = xv.y + 0.1f * (-e1 + v1 * (1.0f - t1 * t1));
                            *(float2*)(g->xs_out + off) = make_float2(xn0, xn1);
                            split2(tanhf(xn0), tanhf(xn1), g->o2h, g->o2l, off);
                        }
                    }
        }
        if (!more) return;
        g = gn; gi = gin; row0 = row0n; col0 = col0n;
    }
}

// ------------------------------ preprocessing ------------------------------
__global__ void k_zero_ticks() { if (threadIdx.x < 64) g_tick[threadIdx.x] = 0u; }

// vectorized split: n must be divisible by 4
__global__ void k_split4(const float* __restrict__ x, h16* __restrict__ h,
                         h16* __restrict__ l, int n4) {
    int i = blockIdx.x * 256 + threadIdx.x;
    if (i < n4) {
        float4 v = ((const float4*)x)[i];
        h162 h0, h1, l0, l1;
        h0.x = __float2half_rn(v.x); h0.y = __float2half_rn(v.y);
        h1.x = __float2half_rn(v.z); h1.y = __float2half_rn(v.w);
        l0.x = __float2half_rn(v.x - __half2float(h0.x));
        l0.y = __float2half_rn(v.y - __half2float(h0.y));
        l1.x = __float2half_rn(v.z - __half2float(h1.x));
        l1.y = __float2half_rn(v.w - __half2float(h1.y));
        ((h162*)h)[i*2] = h0; ((h162*)h)[i*2+1] = h1;
        ((h162*)l)[i*2] = l0; ((h162*)l)[i*2+1] = l1;
    }
}
__global__ void k_split_pad(const float* __restrict__ x, h16* __restrict__ h,
                            h16* __restrict__ l, int rows, int cols, int ldo) {
    int i = blockIdx.x * 256 + threadIdx.x;
    if (i < rows * cols) {
        int r = i / cols, c = i - r * cols;
        float v = x[i];
        h16 a = __float2half_rn(v);
        size_t o = (size_t)r * ldo + c;
        h[o] = a; l[o] = __float2half_rn(v - __half2float(a));
    }
}
__global__ void k_tsplit(const float* __restrict__ w, h16* __restrict__ th,
                         h16* __restrict__ tl, int K, int N) {
    __shared__ float t[32][33];
    int bx = blockIdx.x * 32, by = blockIdx.y * 32;
    int x = threadIdx.x, y = threadIdx.y;
    for (int yy = y; yy < 32; yy += 8) {
        int k = by + yy, n = bx + x;
        t[yy][x] = (k < K && n < N) ? w[(size_t)k * N + n] : 0.0f;
    }
    __syncthreads();
    for (int yy = y; yy < 32; yy += 8) {
        int n = bx + yy, k = by + x;
        if (n < N && k < K) {
            float v = t[x][yy];
            h16 a = __float2half_rn(v);
            size_t o = (size_t)n * K + k;
            th[o] = a; tl[o] = __float2half_rn(v - __half2float(a));
        }
    }
}
__global__ void k_pack(const float* __restrict__ xs4, float* __restrict__ out) {
    int i = blockIdx.x * 256 + threadIdx.x;
    if (i < NB * S4) { int mm = i / S4, n = i - mm * S4; out[i] = xs4[(size_t)mm * S4P + n]; }
}

// ---------------------------------- host -----------------------------------
template <typename T, size_t N>
static T* sym(T (&arr)[N]) { void* p = nullptr; cudaGetSymbolAddress(&p, arr); return (T*)p; }

static void fill_sub(SubG& s,
                     const h16* Ah, const h16* Al, const h16* Bh, const h16* Bl,
                     int K, int N, const float* bias, const float* xs_in, float* xs_out,
                     const h16* esh, const h16* esl, const h16* txh, const h16* txl,
                     h16* o1h, h16* o1l, h16* o2h, h16* o2l,
                     uint32_t nk0, uint32_t nk1, int& cta)
{
    s.Ah = Ah; s.Al = Al; s.Bh = Bh; s.Bl = Bl;
    s.bias = bias; s.xs_in = xs_in; s.xs_out = xs_out;
    s.esh = esh; s.esl = esl; s.txh = txh; s.txl = txl;
    s.o1h = o1h; s.o1l = o1l; s.o2h = o2h; s.o2l = o2l;
    s.K = K; s.N = N; s.beg = cta; s.nx = N / 128;
    s.nk0 = nk0; s.nk1 = nk1;
    cta += (N / 128) * (NB / 128);
}

extern "C" void kernel_launch(void* const* d_in, const int* in_sizes, int n_in,
                              void* d_out, int out_size)
{
    const float* obs = (const float*)d_in[0];
    const float* W1 = (const float*)d_in[1]; const float* b1 = (const float*)d_in[2];
    const float* W2 = (const float*)d_in[3]; const float* b2 = (const float*)d_in[4];
    const float* W3 = (const float*)d_in[5]; const float* b3 = (const float*)d_in[6];
    const float* W4 = (const float*)d_in[7]; const float* b4 = (const float*)d_in[8];

    float *xs1 = sym(g_xs1), *xs2 = sym(g_xs2), *xs3 = sym(g_xs3), *xs4 = sym(g_xs4);
    h16 *tx1h = sym(g_tx1h), *tx1l = sym(g_tx1l), *tx2h = sym(g_tx2h), *tx2l = sym(g_tx2l);
    h16 *tx3h = sym(g_tx3h), *tx3l = sym(g_tx3l), *tx4h = sym(g_tx4h), *tx4l = sym(g_tx4l);
    h16 *es0h = sym(g_es0h), *es0l = sym(g_es0l), *es1h = sym(g_es1h), *es1l = sym(g_es1l);
    h16 *es2h = sym(g_es2h), *es2l = sym(g_es2l), *es3h = sym(g_es3h), *es3l = sym(g_es3l);
    h16 *obsh = sym(g_obsh), *obsl = sym(g_obsl);
    h16 *w1h = sym(g_w1h), *w1l = sym(g_w1l), *w2h = sym(g_w2h), *w2l = sym(g_w2l);
    h16 *w3h = sym(g_w3h), *w3l = sym(g_w3l), *w4h = sym(g_w4h), *w4l = sym(g_w4l);
    h16 *w1th = sym(g_w1th), *w1tl = sym(g_w1tl), *w2th = sym(g_w2th), *w2tl = sym(g_w2tl);
    h16 *w3th = sym(g_w3th), *w3tl = sym(g_w3tl), *w4th = sym(g_w4th), *w4tl = sym(g_w4tl);

    cudaFuncSetAttribute(gemm_b<0>, cudaFuncAttributeMaxDynamicSharedMemorySize, SMEM_SZ);
    cudaFuncSetAttribute(gemm_b<1>, cudaFuncAttributeMaxDynamicSharedMemorySize, SMEM_SZ);
    cudaFuncSetAttribute(gemm_b<2>, cudaFuncAttributeMaxDynamicSharedMemorySize, SMEM_SZ);

    int slot = 0;
    const dim3 tb(32, 8);
    k_zero_ticks<<<1, 64>>>();
    // weight / input preprocessing (constant per launch), vectorized x4
    k_split4<<<(NB*S0/4 + 255)/256, 256>>>(obs, obsh, obsl, NB*S0/4);
    k_split4<<<(S0*S1/4 + 255)/256, 256>>>(W1, w1h, w1l, S0*S1/4);
    k_split4<<<(S1*S2/4 + 255)/256, 256>>>(W2, w2h, w2l, S1*S2/4);
    k_split4<<<(S2*S3/4 + 255)/256, 256>>>(W3, w3h, w3l, S2*S3/4);
    k_split_pad<<<(S3*S4 + 255)/256, 256>>>(W4, w4h, w4l, S3, S4, S4P);
    k_tsplit<<<dim3(S1/32, S0/32), tb>>>(W1, w1th, w1tl, S0, S1);
    k_tsplit<<<dim3(S2/32, S1/32), tb>>>(W2, w2th, w2tl, S1, S2);
    k_tsplit<<<dim3(S3/32, S2/32), tb>>>(W3, w3th, w3tl, S2, S3);
    k_tsplit<<<dim3((S4+31)/32, S3/32), tb>>>(W4, w4th, w4tl, S3, S4);

    // ---- init chain (sequential): xs_i = xs_{i-1} @ W_i ----
    {
        Phase ph; ph.nscale = 0.f; ph.nsub = 1; int cta;
        cta = 0; fill_sub(ph.g[0], obsh, obsl, w1th, w1tl, S0, S1, nullptr, nullptr, xs1,
                          nullptr, nullptr, nullptr, nullptr, es1h, es1l, tx1h, tx1l, 0u, 0u, cta);
        ph.slot = slot++; ph.total = cta;
        gemm_b<0><<<GRID_P, 256, SMEM_SZ>>>(ph);
        cta = 0; fill_sub(ph.g[0], es1h, es1l, w2th, w2tl, S1, S2, nullptr, nullptr, xs2,
                          nullptr, nullptr, nullptr, nullptr, es2h, es2l, tx2h, tx2l, 0u, 0u, cta);
        ph.slot = slot++; ph.total = cta;
        gemm_b<0><<<GRID_P, 256, SMEM_SZ>>>(ph);
        cta = 0; fill_sub(ph.g[0], es2h, es2l, w3th, w3tl, S2, S3, nullptr, nullptr, xs3,
                          nullptr, nullptr, nullptr, nullptr, es3h, es3l, tx3h, tx3l, 0u, 0u, cta);
        ph.slot = slot++; ph.total = cta;
        gemm_b<0><<<GRID_P, 256, SMEM_SZ>>>(ph);
        cta = 0; fill_sub(ph.g[0], es3h, es3l, w4th, w4tl, S3, S4P, nullptr, nullptr, xs4,
                          nullptr, nullptr, nullptr, nullptr, nullptr, nullptr, tx4h, tx4l, 0u, 0u, cta);
        ph.slot = slot++; ph.total = cta;
        gemm_b<0><<<GRID_P, 256, SMEM_SZ>>>(ph);
    }

    for (int i = 0; i < STEPS; i++) {
        float nscale = 0.034f * (1.0f - (float)i / 20.0f);
        uint32_t ki0, ki1, kl0[4], kl1[4];
        threefry2x32(0u, 42u, 0u, (uint32_t)i, ki0, ki1);
        for (int li = 0; li < 4; li++) threefry2x32(ki0, ki1, 0u, (uint32_t)li, kl0[li], kl1[li]);

        // ---- top-down (4 independent NT GEMMs, one launch; largest K first)
        {
            Phase ph; ph.nscale = nscale; ph.nsub = 4; int cta = 0;
            fill_sub(ph.g[0], tx2h, tx2l, w2h, w2l, S2,  S1, b2, xs1, nullptr,
                     nullptr, nullptr, nullptr, nullptr, es1h, es1l, nullptr, nullptr,
                     kl0[1], kl1[1], cta);
            fill_sub(ph.g[1], tx1h, tx1l, w1h, w1l, S1,  S0, b1, obs, nullptr,
                     nullptr, nullptr, nullptr, nullptr, es0h, es0l, nullptr, nullptr,
                     kl0[0], kl1[0], cta);
            fill_sub(ph.g[2], tx3h, tx3l, w3h, w3l, S3,  S2, b3, xs2, nullptr,
                     nullptr, nullptr, nullptr, nullptr, es2h, es2l, nullptr, nullptr,
                     kl0[2], kl1[2], cta);
            fill_sub(ph.g[3], tx4h, tx4l, w4h, w4l, S4P, S3, b4, xs3, nullptr,
                     nullptr, nullptr, nullptr, nullptr, es3h, es3l, nullptr, nullptr,
                     kl0[3], kl1[3], cta);
            ph.slot = slot++; ph.total = cta;
            gemm_b<1><<<GRID_P, 256, SMEM_SZ>>>(ph);
        }
        // ---- bottom-up (4 independent NN GEMMs, one launch; largest K first)
        {
            Phase ph; ph.nscale = 0.f; ph.nsub = 4; int cta = 0;
            fill_sub(ph.g[0], es1h, es1l, w2th, w2tl, S1, S2, nullptr, xs2, xs2,
                     es2h, es2l, tx2h, tx2l, nullptr, nullptr, tx2h, tx2l, 0u, 0u, cta);
            fill_sub(ph.g[1], es2h, es2l, w3th, w3tl, S2, S3, nullptr, xs3, xs3,
                     es3h, es3l, tx3h, tx3l, nullptr, nullptr, tx3h, tx3l, 0u, 0u, cta);
            fill_sub(ph.g[2], es0h, es0l, w1th, w1tl, S0, S1, nullptr, xs1, xs1,
                     es1h, es1l, tx1h, tx1l, nullptr, nullptr, tx1h, tx1l, 0u, 0u, cta);
            fill_sub(ph.g[3], es3h, es3l, w4th, w4tl, S3, S4P, nullptr, xs4, xs4,
                     nullptr, nullptr, tx4h, tx4l, nullptr, nullptr, tx4h, tx4l, 0u, 0u, cta);
            ph.slot = slot++; ph.total = cta;
            gemm_b<2><<<GRID_P, 256, SMEM_SZ>>>(ph);
        }
    }
    k_pack<<<(NB*S4 + 255)/256, 256>>>(xs4, (float*)d_out);
}

// round 17
// speedup vs baseline: 1.1728x; 1.1496x over previous
#include <cuda_runtime.h>
#include <cuda_fp16.h>
#include <cstdint>

using h16  = __half;
using h162 = __half2;

#define S0 3072
#define S1 4096
#define S2 4096
#define S3 2048
#define S4 1000
#define S4P 1024
#define NB 1024
#define STEPS 20

#define TILE_B    16384                    // 128 rows x 128B (one operand tile)
#define BUF_BYTES (4 * TILE_B)             // Ah, Al, Bh, Bl = 65536
#define NSTAGE    3
#define SMEM_SZ   (1024 + NSTAGE * BUF_BYTES)
#define GRID_P    152

#define DEVARR __device__ __align__(16)

// ------------------------- persistent state (zero-init) --------------------
DEVARR float g_xs1[NB*S1];
DEVARR float g_xs2[NB*S2];
DEVARR float g_xs3[NB*S3];
DEVARR float g_xs4[NB*S4P];                 // padded; pad cols stay 0
DEVARR h16 g_tx1h[NB*S1], g_tx1l[NB*S1];
DEVARR h16 g_tx2h[NB*S2], g_tx2l[NB*S2];
DEVARR h16 g_tx3h[NB*S3], g_tx3l[NB*S3];
DEVARR h16 g_tx4h[NB*S4P], g_tx4l[NB*S4P]; // pad cols stay 0
DEVARR h16 g_es0h[NB*S0], g_es0l[NB*S0];
DEVARR h16 g_es1h[NB*S1], g_es1l[NB*S1];   // init chain: split of raw xs1
DEVARR h16 g_es2h[NB*S2], g_es2l[NB*S2];
DEVARR h16 g_es3h[NB*S3], g_es3l[NB*S3];
DEVARR h16 g_obsh[NB*S0], g_obsl[NB*S0];
// NT weights: W_i as [N=sizes[i-1], K=sizes[i]] (K-major)
DEVARR h16 g_w1h[S0*S1], g_w1l[S0*S1];
DEVARR h16 g_w2h[S1*S2], g_w2l[S1*S2];
DEVARR h16 g_w3h[S2*S3], g_w3l[S2*S3];
DEVARR h16 g_w4h[S3*S4P], g_w4l[S3*S4P];   // K padded, pad cols 0
// NN weights: W_i^T as [N=sizes[i], K=sizes[i-1]]
DEVARR h16 g_w1th[S1*S0], g_w1tl[S1*S0];
DEVARR h16 g_w2th[S2*S1], g_w2tl[S2*S1];
DEVARR h16 g_w3th[S3*S2], g_w3tl[S3*S2];
DEVARR h16 g_w4th[S4P*S3], g_w4tl[S4P*S3]; // N padded, pad rows 0

__device__ unsigned g_tick[64];             // per-launch ticket counters

// ------------------------------- PTX helpers -------------------------------
__device__ __forceinline__ uint32_t s2u(const void* p) {
    uint32_t a;
    asm("{ .reg .u64 t; cvta.to.shared.u64 t, %1; cvt.u32.u64 %0, t; }" : "=r"(a) : "l"(p));
    return a;
}
__device__ __forceinline__ void cp16(uint32_t d, const void* s) {
    asm volatile("cp.async.cg.shared.global [%0], [%1], 16;" :: "r"(d), "l"(s));
}
__device__ __forceinline__ void cp_commit() { asm volatile("cp.async.commit_group;" ::: "memory"); }
template <int N> __device__ __forceinline__ void cp_wait() {
    asm volatile("cp.async.wait_group %0;" :: "n"(N) : "memory");
}
__device__ __forceinline__ void ldsm4(uint32_t* r, uint32_t addr) {
    asm volatile("ldmatrix.sync.aligned.m8n8.x4.shared.b16 {%0,%1,%2,%3}, [%4];"
                 : "=r"(r[0]), "=r"(r[1]), "=r"(r[2]), "=r"(r[3]) : "r"(addr));
}
// main term: fp16 inputs, fp32 accumulator (products exact: 11+11 < 24 bits)
__device__ __forceinline__ void mma_f32acc(float* d, const uint32_t* a,
                                           uint32_t b0, uint32_t b1) {
    asm volatile("mma.sync.aligned.m16n8k16.row.col.f32.f16.f16.f32 "
                 "{%0,%1,%2,%3}, {%4,%5,%6,%7}, {%8,%9}, {%0,%1,%2,%3};"
                 : "+f"(d[0]), "+f"(d[1]), "+f"(d[2]), "+f"(d[3])
                 : "r"(a[0]), "r"(a[1]), "r"(a[2]), "r"(a[3]), "r"(b0), "r"(b1));
}
// cross terms: fp16 inputs, fp16 accumulator (equal rate; fewer acc regs)
__device__ __forceinline__ void mma_f16acc(uint32_t* d, const uint32_t* a,
                                           uint32_t b0, uint32_t b1) {
    asm volatile("mma.sync.aligned.m16n8k16.row.col.f16.f16.f16.f16 "
                 "{%0,%1}, {%2,%3,%4,%5}, {%6,%7}, {%0,%1};"
                 : "+r"(d[0]), "+r"(d[1])
                 : "r"(a[0]), "r"(a[1]), "r"(a[2]), "r"(a[3]), "r"(b0), "r"(b1));
}

// --------------------- JAX threefry + normal (verified) --------------------
__host__ __device__ __forceinline__ uint32_t rotl32(uint32_t v, int s) {
#ifdef __CUDA_ARCH__
    return __funnelshift_l(v, v, s);
#else
    return (v << s) | (v >> (32 - s));
#endif
}
__host__ __device__ __forceinline__ void threefry2x32(
    uint32_t k0, uint32_t k1, uint32_t c0, uint32_t c1, uint32_t& o0, uint32_t& o1)
{
    uint32_t k2 = k0 ^ k1 ^ 0x1BD11BDAu;
    uint32_t x0 = c0 + k0, x1 = c1 + k1;
#define TF_R4(ra, rb, rc, rd)                          \
    x0 += x1; x1 = rotl32(x1, ra); x1 ^= x0;           \
    x0 += x1; x1 = rotl32(x1, rb); x1 ^= x0;           \
    x0 += x1; x1 = rotl32(x1, rc); x1 ^= x0;           \
    x0 += x1; x1 = rotl32(x1, rd); x1 ^= x0;
    TF_R4(13,15,26,6)  x0 += k1; x1 += k2 + 1u;
    TF_R4(17,29,16,24) x0 += k2; x1 += k0 + 2u;
    TF_R4(13,15,26,6)  x0 += k0; x1 += k1 + 3u;
    TF_R4(17,29,16,24) x0 += k1; x1 += k2 + 4u;
    TF_R4(13,15,26,6)  x0 += k2; x1 += k0 + 5u;
#undef TF_R4
    o0 = x0; o1 = x1;
}
__device__ __forceinline__ float erfinv_f32(float x) {
    float w = -log1pf(-x * x), p;
    if (w < 5.0f) {
        w -= 2.5f;
        p = 2.81022636e-08f;
        p = fmaf(p, w, 3.43273939e-07f);  p = fmaf(p, w, -3.5233877e-06f);
        p = fmaf(p, w, -4.39150654e-06f); p = fmaf(p, w, 0.00021858087f);
        p = fmaf(p, w, -0.00125372503f);  p = fmaf(p, w, -0.00417768164f);
        p = fmaf(p, w, 0.246640727f);     p = fmaf(p, w, 1.50140941f);
    } else {
        w = sqrtf(w) - 3.0f;
        p = -0.000200214257f;
        p = fmaf(p, w, 0.000100950558f);  p = fmaf(p, w, 0.00134934322f);
        p = fmaf(p, w, -0.00367342844f);  p = fmaf(p, w, 0.00573950773f);
        p = fmaf(p, w, -0.0076224613f);   p = fmaf(p, w, 0.00943887047f);
        p = fmaf(p, w, 1.00167406f);      p = fmaf(p, w, 2.83297682f);
    }
    return p * x;
}
__device__ __forceinline__ float jax_normal_elem(uint32_t k0, uint32_t k1, uint32_t j) {
    uint32_t x0, x1;
    threefry2x32(k0, k1, 0u, j, x0, x1);
    uint32_t bits = x0 ^ x1;
    float f = __uint_as_float((bits >> 9) | 0x3f800000u) - 1.0f;
    float u = fmaxf(-0.99999994f, f * 2.0f + (-0.99999994f));
    return 1.41421356f * erfinv_f32(u);
}

// ------------------------------ split helper -------------------------------
__device__ __forceinline__ void split2(float a, float b, h16* h, h16* l, size_t off) {
    h16 ha = __float2half_rn(a), hb = __float2half_rn(b);
    h162 hv; hv.x = ha; hv.y = hb;
    *(h162*)(h + off) = hv;
    h162 lv;
    lv.x = __float2half_rn(a - __half2float(ha));
    lv.y = __float2half_rn(b - __half2float(hb));
    *(h162*)(l + off) = lv;
}

// ------------------- smem tile load (128B rows, 16B xor swizzle) -----------
__device__ __forceinline__ void load_tile(const h16* g, int row0, int K, int c,
                                          uint32_t sdst, int tid) {
    const char* gp = (const char*)(g + (size_t)row0 * K) + (size_t)c * 128;
    const size_t strideB = (size_t)K * 2;
#pragma unroll
    for (int i = tid; i < 128 * 8; i += 256) {
        int r = i >> 3, u = i & 7;
        cp16(sdst + r * 128 + ((u ^ (r & 7)) << 4), gp + (size_t)r * strideB + u * 16);
    }
}

// ------------------------- batched sub-GEMM descriptors --------------------
struct SubG {
    const h16 *Ah, *Al, *Bh, *Bl;
    const float *bias, *xs_in;
    float *xs_out;
    const h16 *esh, *esl, *txh, *txl;
    h16 *o1h, *o1l, *o2h, *o2l;
    int K, N, beg, nx;
    uint32_t nk0, nk1;
};
struct Phase { SubG g[4]; float nscale; int nsub; int slot; int total; };

// LOAD_AL=false skips the A-lo tile (EPI2: Al@Bh pass dropped)
template <bool LOAD_AL>
__device__ __forceinline__ void load_chunk_g(const SubG* g, int row0, int col0,
                                             int c, uint32_t buf, int tid) {
    load_tile(g->Ah, row0, g->K, c, buf, tid);
    if (LOAD_AL) load_tile(g->Al, row0, g->K, c, buf + TILE_B, tid);
    load_tile(g->Bh, col0, g->K, c, buf + 2*TILE_B, tid);
    load_tile(g->Bl, col0, g->K, c, buf + 3*TILE_B, tid);
    cp_commit();
}

// ---------------------------------------------------------------------------
// gemm_b<EPI>: persistent CTAs, atomic-ticket tiles, cross-tile prefetch.
// CTA tile 128x128, warp tile 32x64.
// EPI 0: init  D = AhBh + AhBl + AlBh; xs_out=D; o1=split(D); o2=split(tanh D)
// EPI 1: NT es (3-term)  e = xs_in - (D+bias) + noise*nscale; o1=split(e)
// EPI 2: NN    (2-term: AhBh + AhBl — es-lo x W-hi dropped; damped by 0.1)
//              xn = xs + 0.1*(-es + D*(1-t^2)); xs=xn; o2=split(tanh(xn))
// ---------------------------------------------------------------------------
template <int EPI>
__global__ void __launch_bounds__(256, 1) gemm_b(const __grid_constant__ Phase d)
{
    constexpr bool THREE = (EPI != 2);       // third (Al@Bh) pass on?
    extern __shared__ char smem[];
    __shared__ int s_tile;
    const uint32_t sb = (s2u(smem) + 1023u) & ~1023u;
    const int tid = threadIdx.x;
    const int warp = tid >> 5, lane = tid & 31;
    const int wm = warp & 3, wn = warp >> 2;   // warp tile: 32 rows x 64 cols
    const int lr = lane & 15, lu = lane >> 4;

    // ---- first ticket ----
    if (tid == 0) s_tile = (int)atomicAdd(&g_tick[d.slot], 1u);
    __syncthreads();
    int t = s_tile;
    if (t >= d.total) return;

    int gi = 0;
#pragma unroll
    for (int i = 1; i < 4; i++)
        if (i < d.nsub && t >= d.g[i].beg) gi = i;
    const SubG* g = &d.g[gi];
    int local = t - g->beg;
    int row0 = (local / g->nx) * 128;
    int col0 = (local % g->nx) * 128;

    int stage = 0;
    load_chunk_g<THREE>(g, row0, col0, 0, sb, tid);
    load_chunk_g<THREE>(g, row0, col0, 1, sb + BUF_BYTES, tid);

    float acc[2][8][4];          // main term, f32
    uint32_t xacc[2][8][2];      // shared cross-term acc, f16x2 pairs

    for (;;) {
#pragma unroll
        for (int a = 0; a < 2; a++)
#pragma unroll
            for (int b = 0; b < 8; b++) {
#pragma unroll
                for (int e = 0; e < 4; e++) acc[a][b][e] = 0.0f;
                xacc[a][b][0] = 0u; xacc[a][b][1] = 0u;
            }

        // -------------------------- mainloop -------------------------------
        const int NC = g->K >> 6;
        for (int c = 0; c < NC; c++) {
            if (c + 1 < NC) cp_wait<1>(); else cp_wait<0>();
            __syncthreads();
            if (c + 2 < NC) {
                int ns = stage + 2; if (ns >= NSTAGE) ns -= NSTAGE;
                load_chunk_g<THREE>(g, row0, col0, c + 2, sb + (uint32_t)ns * BUF_BYTES, tid);
            }
            const uint32_t buf = sb + (uint32_t)stage * BUF_BYTES;
#pragma unroll
            for (int ks = 0; ks < 4; ks++) {
                const int u = ks * 2 + lu;
                uint32_t ah[2][4], al[2][4], bh[4][4], bl[4][4];
#pragma unroll
                for (int mf = 0; mf < 2; mf++) {
                    const int r = wm * 32 + mf * 16 + lr;
                    const uint32_t sw = (uint32_t)r * 128u + (uint32_t)((u ^ (r & 7)) << 4);
                    ldsm4(ah[mf], buf + sw);
                    if (THREE) ldsm4(al[mf], buf + TILE_B + sw);
                }
#pragma unroll
                for (int nfp = 0; nfp < 4; nfp++) {
                    const int rn = wn * 64 + nfp * 16 + lr;
                    const uint32_t sw = (uint32_t)rn * 128u + (uint32_t)((u ^ (rn & 7)) << 4);
                    ldsm4(bh[nfp], buf + 2*TILE_B + sw);
                    ldsm4(bl[nfp], buf + 3*TILE_B + sw);
                }
#pragma unroll
                for (int mf = 0; mf < 2; mf++)
#pragma unroll
                    for (int nfp = 0; nfp < 4; nfp++)
#pragma unroll
                        for (int h = 0; h < 2; h++)
                            mma_f32acc(acc[mf][nfp*2+h], ah[mf], bh[nfp][h], bh[nfp][h+2]);
#pragma unroll
                for (int mf = 0; mf < 2; mf++)
#pragma unroll
                    for (int nfp = 0; nfp < 4; nfp++)
#pragma unroll
                        for (int h = 0; h < 2; h++)
                            mma_f16acc(xacc[mf][nfp*2+h], ah[mf], bl[nfp][h], bl[nfp][h+2]);
                if (THREE) {
#pragma unroll
                    for (int mf = 0; mf < 2; mf++)
#pragma unroll
                        for (int nfp = 0; nfp < 4; nfp++)
#pragma unroll
                            for (int h = 0; h < 2; h++)
                                mma_f16acc(xacc[mf][nfp*2+h], al[mf], bh[nfp][h], bh[nfp][h+2]);
                }
            }
            if (++stage >= NSTAGE) stage = 0;
        }

        // ---- fetch NEXT ticket; prefetch its first 2 chunks during epilogue
        if (tid == 0) s_tile = (int)atomicAdd(&g_tick[d.slot], 1u);
        __syncthreads();                    // closes mainloop smem reads
        const int tn = s_tile;
        const bool more = (tn < d.total);
        const SubG* gn = g;
        int gin = gi, row0n = row0, col0n = col0;
        if (more) {
            gin = 0;
#pragma unroll
            for (int i = 1; i < 4; i++)
                if (i < d.nsub && tn >= d.g[i].beg) gin = i;
            gn = &d.g[gin];
            int ln = tn - gn->beg;
            row0n = (ln / gn->nx) * 128;
            col0n = (ln % gn->nx) * 128;
            int s1 = stage + 1; if (s1 >= NSTAGE) s1 -= NSTAGE;
            load_chunk_g<THREE>(gn, row0n, col0n, 0, sb + (uint32_t)stage * BUF_BYTES, tid);
            load_chunk_g<THREE>(gn, row0n, col0n, 1, sb + (uint32_t)s1 * BUF_BYTES, tid);
        }

        // --------------------------- fused epilogue ------------------------
        {
            const int N = g->N;
            const int mb = row0 + wm * 32 + (lane >> 2);
            const int nb = col0 + wn * 64 + (lane & 3) * 2;
#pragma unroll
            for (int mf = 0; mf < 2; mf++)
#pragma unroll
                for (int nf = 0; nf < 8; nf++)
#pragma unroll
                    for (int eh = 0; eh < 2; eh++) {
                        const int m = mb + mf * 16 + eh * 8;
                        const int n = nb + nf * 8;
                        h162 x2 = *(const h162*)&xacc[mf][nf][eh];
                        float v0 = acc[mf][nf][eh * 2]     + __half2float(x2.x);
                        float v1 = acc[mf][nf][eh * 2 + 1] + __half2float(x2.y);
                        const size_t off = (size_t)m * N + n;
                        if (EPI == 0) {
                            g->xs_out[off] = v0; g->xs_out[off + 1] = v1;
                            if (g->o1h) split2(v0, v1, g->o1h, g->o1l, off);
                            split2(tanhf(v0), tanhf(v1), g->o2h, g->o2l, off);
                        } else if (EPI == 1) {
                            float2 xv = *(const float2*)(g->xs_in + off);
                            float p0 = v0 + g->bias[n], p1 = v1 + g->bias[n + 1];
                            float z0 = jax_normal_elem(g->nk0, g->nk1, (uint32_t)off);
                            float z1 = jax_normal_elem(g->nk0, g->nk1, (uint32_t)off + 1u);
                            split2((xv.x - p0) + z0 * d.nscale, (xv.y - p1) + z1 * d.nscale,
                                   g->o1h, g->o1l, off);
                        } else {
                            float2 xv = *(const float2*)(g->xs_in + off);
                            h162 th2 = *(const h162*)(g->txh + off), tl2 = *(const h162*)(g->txl + off);
                            float t0 = __half2float(th2.x) + __half2float(tl2.x);
                            float t1 = __half2float(th2.y) + __half2float(tl2.y);
                            float e0 = 0.f, e1 = 0.f;
                            if (g->esh) {
                                h162 eh2 = *(const h162*)(g->esh + off), el2 = *(const h162*)(g->esl + off);
                                e0 = __half2float(eh2.x) + __half2float(el2.x);
                                e1 = __half2float(eh2.y) + __half2float(el2.y);
                            }
                            float xn0 = xv.x + 0.1f * (-e0 + v0 * (1.0f - t0 * t0));
                            float xn1 = xv.y + 0.1f * (-e1 + v1 * (1.0f - t1 * t1));
                            *(float2*)(g->xs_out + off) = make_float2(xn0, xn1);
                            split2(tanhf(xn0), tanhf(xn1), g->o2h, g->o2l, off);
                        }
                    }
        }
        if (!more) return;
        g = gn; gi = gin; row0 = row0n; col0 = col0n;
    }
}

// ------------------------------ preprocessing ------------------------------
__global__ void k_zero_ticks() { if (threadIdx.x < 64) g_tick[threadIdx.x] = 0u; }

__global__ void k_split4(const float* __restrict__ x, h16* __restrict__ h,
                         h16* __restrict__ l, int n4) {
    int i = blockIdx.x * 256 + threadIdx.x;
    if (i < n4) {
        float4 v = ((const float4*)x)[i];
        h162 h0, h1, l0, l1;
        h0.x = __float2half_rn(v.x); h0.y = __float2half_rn(v.y);
        h1.x = __float2half_rn(v.z); h1.y = __float2half_rn(v.w);
        l0.x = __float2half_rn(v.x - __half2float(h0.x));
        l0.y = __float2half_rn(v.y - __half2float(h0.y));
        l1.x = __float2half_rn(v.z - __half2float(h1.x));
        l1.y = __float2half_rn(v.w - __half2float(h1.y));
        ((h162*)h)[i*2] = h0; ((h162*)h)[i*2+1] = h1;
        ((h162*)l)[i*2] = l0; ((h162*)l)[i*2+1] = l1;
    }
}
__global__ void k_split_pad(const float* __restrict__ x, h16* __restrict__ h,
                            h16* __restrict__ l, int rows, int cols, int ldo) {
    int i = blockIdx.x * 256 + threadIdx.x;
    if (i < rows * cols) {
        int r = i / cols, c = i - r * cols;
        float v = x[i];
        h16 a = __float2half_rn(v);
        size_t o = (size_t)r * ldo + c;
        h[o] = a; l[o] = __float2half_rn(v - __half2float(a));
    }
}
__global__ void k_tsplit(const float* __restrict__ w, h16* __restrict__ th,
                         h16* __restrict__ tl, int K, int N) {
    __shared__ float t[32][33];
    int bx = blockIdx.x * 32, by = blockIdx.y * 32;
    int x = threadIdx.x, y = threadIdx.y;
    for (int yy = y; yy < 32; yy += 8) {
        int k = by + yy, n = bx + x;
        t[yy][x] = (k < K && n < N) ? w[(size_t)k * N + n] : 0.0f;
    }
    __syncthreads();
    for (int yy = y; yy < 32; yy += 8) {
        int n = bx + yy, k = by + x;
        if (n < N && k < K) {
            float v = t[x][yy];
            h16 a = __float2half_rn(v);
            size_t o = (size_t)n * K + k;
            th[o] = a; tl[o] = __float2half_rn(v - __half2float(a));
        }
    }
}
__global__ void k_pack(const float* __restrict__ xs4, float* __restrict__ out) {
    int i = blockIdx.x * 256 + threadIdx.x;
    if (i < NB * S4) { int mm = i / S4, n = i - mm * S4; out[i] = xs4[(size_t)mm * S4P + n]; }
}

// ---------------------------------- host -----------------------------------
template <typename T, size_t N>
static T* sym(T (&arr)[N]) { void* p = nullptr; cudaGetSymbolAddress(&p, arr); return (T*)p; }

static void fill_sub(SubG& s,
                     const h16* Ah, const h16* Al, const h16* Bh, const h16* Bl,
                     int K, int N, const float* bias, const float* xs_in, float* xs_out,
                     const h16* esh, const h16* esl, const h16* txh, const h16* txl,
                     h16* o1h, h16* o1l, h16* o2h, h16* o2l,
                     uint32_t nk0, uint32_t nk1, int& cta)
{
    s.Ah = Ah; s.Al = Al; s.Bh = Bh; s.Bl = Bl;
    s.bias = bias; s.xs_in = xs_in; s.xs_out = xs_out;
    s.esh = esh; s.esl = esl; s.txh = txh; s.txl = txl;
    s.o1h = o1h; s.o1l = o1l; s.o2h = o2h; s.o2l = o2l;
    s.K = K; s.N = N; s.beg = cta; s.nx = N / 128;
    s.nk0 = nk0; s.nk1 = nk1;
    cta += (N / 128) * (NB / 128);
}

extern "C" void kernel_launch(void* const* d_in, const int* in_sizes, int n_in,
                              void* d_out, int out_size)
{
    const float* obs = (const float*)d_in[0];
    const float* W1 = (const float*)d_in[1]; const float* b1 = (const float*)d_in[2];
    const float* W2 = (const float*)d_in[3]; const float* b2 = (const float*)d_in[4];
    const float* W3 = (const float*)d_in[5]; const float* b3 = (const float*)d_in[6];
    const float* W4 = (const float*)d_in[7]; const float* b4 = (const float*)d_in[8];

    float *xs1 = sym(g_xs1), *xs2 = sym(g_xs2), *xs3 = sym(g_xs3), *xs4 = sym(g_xs4);
    h16 *tx1h = sym(g_tx1h), *tx1l = sym(g_tx1l), *tx2h = sym(g_tx2h), *tx2l = sym(g_tx2l);
    h16 *tx3h = sym(g_tx3h), *tx3l = sym(g_tx3l), *tx4h = sym(g_tx4h), *tx4l = sym(g_tx4l);
    h16 *es0h = sym(g_es0h), *es0l = sym(g_es0l), *es1h = sym(g_es1h), *es1l = sym(g_es1l);
    h16 *es2h = sym(g_es2h), *es2l = sym(g_es2l), *es3h = sym(g_es3h), *es3l = sym(g_es3l);
    h16 *obsh = sym(g_obsh), *obsl = sym(g_obsl);
    h16 *w1h = sym(g_w1h), *w1l = sym(g_w1l), *w2h = sym(g_w2h), *w2l = sym(g_w2l);
    h16 *w3h = sym(g_w3h), *w3l = sym(g_w3l), *w4h = sym(g_w4h), *w4l = sym(g_w4l);
    h16 *w1th = sym(g_w1th), *w1tl = sym(g_w1tl), *w2th = sym(g_w2th), *w2tl = sym(g_w2tl);
    h16 *w3th = sym(g_w3th), *w3tl = sym(g_w3tl), *w4th = sym(g_w4th), *w4tl = sym(g_w4tl);

    cudaFuncSetAttribute(gemm_b<0>, cudaFuncAttributeMaxDynamicSharedMemorySize, SMEM_SZ);
    cudaFuncSetAttribute(gemm_b<1>, cudaFuncAttributeMaxDynamicSharedMemorySize, SMEM_SZ);
    cudaFuncSetAttribute(gemm_b<2>, cudaFuncAttributeMaxDynamicSharedMemorySize, SMEM_SZ);

    int slot = 0;
    const dim3 tb(32, 8);
    k_zero_ticks<<<1, 64>>>();
    // weight / input preprocessing (constant per launch), vectorized x4
    k_split4<<<(NB*S0/4 + 255)/256, 256>>>(obs, obsh, obsl, NB*S0/4);
    k_split4<<<(S0*S1/4 + 255)/256, 256>>>(W1, w1h, w1l, S0*S1/4);
    k_split4<<<(S1*S2/4 + 255)/256, 256>>>(W2, w2h, w2l, S1*S2/4);
    k_split4<<<(S2*S3/4 + 255)/256, 256>>>(W3, w3h, w3l, S2*S3/4);
    k_split_pad<<<(S3*S4 + 255)/256, 256>>>(W4, w4h, w4l, S3, S4, S4P);
    k_tsplit<<<dim3(S1/32, S0/32), tb>>>(W1, w1th, w1tl, S0, S1);
    k_tsplit<<<dim3(S2/32, S1/32), tb>>>(W2, w2th, w2tl, S1, S2);
    k_tsplit<<<dim3(S3/32, S2/32), tb>>>(W3, w3th, w3tl, S2, S3);
    k_tsplit<<<dim3((S4+31)/32, S3/32), tb>>>(W4, w4th, w4tl, S3, S4);

    // ---- init chain (sequential): xs_i = xs_{i-1} @ W_i ----
    {
        Phase ph; ph.nscale = 0.f; ph.nsub = 1; int cta;
        cta = 0; fill_sub(ph.g[0], obsh, obsl, w1th, w1tl, S0, S1, nullptr, nullptr, xs1,
                          nullptr, nullptr, nullptr, nullptr, es1h, es1l, tx1h, tx1l, 0u, 0u, cta);
        ph.slot = slot++; ph.total = cta;
        gemm_b<0><<<GRID_P, 256, SMEM_SZ>>>(ph);
        cta = 0; fill_sub(ph.g[0], es1h, es1l, w2th, w2tl, S1, S2, nullptr, nullptr, xs2,
                          nullptr, nullptr, nullptr, nullptr, es2h, es2l, tx2h, tx2l, 0u, 0u, cta);
        ph.slot = slot++; ph.total = cta;
        gemm_b<0><<<GRID_P, 256, SMEM_SZ>>>(ph);
        cta = 0; fill_sub(ph.g[0], es2h, es2l, w3th, w3tl, S2, S3, nullptr, nullptr, xs3,
                          nullptr, nullptr, nullptr, nullptr, es3h, es3l, tx3h, tx3l, 0u, 0u, cta);
        ph.slot = slot++; ph.total = cta;
        gemm_b<0><<<GRID_P, 256, SMEM_SZ>>>(ph);
        cta = 0; fill_sub(ph.g[0], es3h, es3l, w4th, w4tl, S3, S4P, nullptr, nullptr, xs4,
                          nullptr, nullptr, nullptr, nullptr, nullptr, nullptr, tx4h, tx4l, 0u, 0u, cta);
        ph.slot = slot++; ph.total = cta;
        gemm_b<0><<<GRID_P, 256, SMEM_SZ>>>(ph);
    }

    for (int i = 0; i < STEPS; i++) {
        float nscale = 0.034f * (1.0f - (float)i / 20.0f);
        uint32_t ki0, ki1, kl0[4], kl1[4];
        threefry2x32(0u, 42u, 0u, (uint32_t)i, ki0, ki1);
        for (int li = 0; li < 4; li++) threefry2x32(ki0, ki1, 0u, (uint32_t)li, kl0[li], kl1[li]);

        // ---- top-down (4 independent NT GEMMs, one launch; largest K first)
        {
            Phase ph; ph.nscale = nscale; ph.nsub = 4; int cta = 0;
            fill_sub(ph.g[0], tx2h, tx2l, w2h, w2l, S2,  S1, b2, xs1, nullptr,
                     nullptr, nullptr, nullptr, nullptr, es1h, es1l, nullptr, nullptr,
                     kl0[1], kl1[1], cta);
            fill_sub(ph.g[1], tx1h, tx1l, w1h, w1l, S1,  S0, b1, obs, nullptr,
                     nullptr, nullptr, nullptr, nullptr, es0h, es0l, nullptr, nullptr,
                     kl0[0], kl1[0], cta);
            fill_sub(ph.g[2], tx3h, tx3l, w3h, w3l, S3,  S2, b3, xs2, nullptr,
                     nullptr, nullptr, nullptr, nullptr, es2h, es2l, nullptr, nullptr,
                     kl0[2], kl1[2], cta);
            fill_sub(ph.g[3], tx4h, tx4l, w4h, w4l, S4P, S3, b4, xs3, nullptr,
                     nullptr, nullptr, nullptr, nullptr, es3h, es3l, nullptr, nullptr,
                     kl0[3], kl1[3], cta);
            ph.slot = slot++; ph.total = cta;
            gemm_b<1><<<GRID_P, 256, SMEM_SZ>>>(ph);
        }
        // ---- bottom-up (4 independent NN GEMMs, one launch; 2-term split)
        {
            Phase ph; ph.nscale = 0.f; ph.nsub = 4; int cta = 0;
            fill_sub(ph.g[0], es1h, es1l, w2th, w2tl, S1, S2, nullptr, xs2, xs2,
                     es2h, es2l, tx2h, tx2l, nullptr, nullptr, tx2h, tx2l, 0u, 0u, cta);
            fill_sub(ph.g[1], es2h, es2l, w3th, w3tl, S2, S3, nullptr, xs3, xs3,
                     es3h, es3l, tx3h, tx3l, nullptr, nullptr, tx3h, tx3l, 0u, 0u, cta);
            fill_sub(ph.g[2], es0h, es0l, w1th, w1tl, S0, S1, nullptr, xs1, xs1,
                     es1h, es1l, tx1h, tx1l, nullptr, nullptr, tx1h, tx1l, 0u, 0u, cta);
            fill_sub(ph.g[3], es3h, es3l, w4th, w4tl, S3, S4P, nullptr, xs4, xs4,
                     nullptr, nullptr, tx4h, tx4l, nullptr, nullptr, tx4h, tx4l, 0u, 0u, cta);
            ph.slot = slot++; ph.total = cta;
            gemm_b<2><<<GRID_P, 256, SMEM_SZ>>>(ph);
        }
    }
    k_pack<<<(NB*S4 + 255)/256, 256>>>(xs4, (float*)d_out);
}